// round 5
// baseline (speedup 1.0000x reference)
#include <cuda_runtime.h>
#include <math.h>

// Problem constants (from setup_inputs): B=4, S=2048, D=1024, H=16, dh=64
#define BATCH 4
#define SEQ   2048
#define DMODEL 1024
#define NHEAD 16
#define DHEAD 64

// Scratch (alloc-free rule: __device__ globals)
__device__ float g_Q[(size_t)BATCH * NHEAD * SEQ * DHEAD]; // [b][h][s][d]
__device__ float g_K[(size_t)BATCH * NHEAD * SEQ * DHEAD];
__device__ float g_V[(size_t)BATCH * NHEAD * SEQ * DHEAD];
__device__ float g_A[(size_t)BATCH * SEQ * DMODEL];        // attn out, [b][s][h*64+d]

// ---------------------------------------------------------------------------
// GEMM: C[m][n] = sum_k X[m][k] * W[n][k]   (X: [8192,1024], W: [1024,1024])
// 128x128 block tile, BK=16, 256 threads, 8x8 per-thread register tile.
// MODE 0 (qkv): z selects Wq/Wk/Wv; epilogue applies RoPE (z<2) and writes
//               scratch in [b][h][s][dh] layout.
// MODE 1 (out): plain row-major store to output.
// ---------------------------------------------------------------------------

__global__ __launch_bounds__(256) void qkv_gemm(const float* __restrict__ X,
                                                const float* __restrict__ Wq,
                                                const float* __restrict__ Wk,
                                                const float* __restrict__ Wv)
{
    __shared__ float As[16][128];
    __shared__ float Bs[16][128];

    const int z = blockIdx.z;
    const float* W = (z == 0) ? Wq : ((z == 1) ? Wk : Wv);
    float* Out = (z == 0) ? g_Q : ((z == 1) ? g_K : g_V);

    const int m0 = blockIdx.y * 128;
    const int n0 = blockIdx.x * 128;
    const int tid = threadIdx.x;
    const int tx = tid & 15, ty = tid >> 4;
    const int lr = tid >> 2;            // 0..63
    const int kc = (tid & 3) * 4;       // 0,4,8,12

    float acc[8][8];
    #pragma unroll
    for (int i = 0; i < 8; i++)
        #pragma unroll
        for (int j = 0; j < 8; j++) acc[i][j] = 0.0f;

    const float* Ap = X + (size_t)(m0 + lr) * DMODEL + kc;
    const float* Bp = W + (size_t)(n0 + lr) * DMODEL + kc;

    for (int kt = 0; kt < DMODEL / 16; kt++) {
        float4 a0 = *(const float4*)(Ap);
        float4 a1 = *(const float4*)(Ap + (size_t)64 * DMODEL);
        float4 b0 = *(const float4*)(Bp);
        float4 b1 = *(const float4*)(Bp + (size_t)64 * DMODEL);
        Ap += 16; Bp += 16;

        __syncthreads();
        As[kc + 0][lr] = a0.x; As[kc + 1][lr] = a0.y;
        As[kc + 2][lr] = a0.z; As[kc + 3][lr] = a0.w;
        As[kc + 0][lr + 64] = a1.x; As[kc + 1][lr + 64] = a1.y;
        As[kc + 2][lr + 64] = a1.z; As[kc + 3][lr + 64] = a1.w;
        Bs[kc + 0][lr] = b0.x; Bs[kc + 1][lr] = b0.y;
        Bs[kc + 2][lr] = b0.z; Bs[kc + 3][lr] = b0.w;
        Bs[kc + 0][lr + 64] = b1.x; Bs[kc + 1][lr + 64] = b1.y;
        Bs[kc + 2][lr + 64] = b1.z; Bs[kc + 3][lr + 64] = b1.w;
        __syncthreads();

        #pragma unroll
        for (int k = 0; k < 16; k++) {
            float a[8], b[8];
            *(float4*)(a)     = *(float4*)&As[k][ty * 8];
            *(float4*)(a + 4) = *(float4*)&As[k][ty * 8 + 4];
            *(float4*)(b)     = *(float4*)&Bs[k][tx * 8];
            *(float4*)(b + 4) = *(float4*)&Bs[k][tx * 8 + 4];
            #pragma unroll
            for (int i = 0; i < 8; i++)
                #pragma unroll
                for (int j = 0; j < 8; j++)
                    acc[i][j] = fmaf(a[i], b[j], acc[i][j]);
        }
    }

    // Epilogue: RoPE (for Q,K) + scatter to [b][h][s][dh]
    const int n = n0 + tx * 8;
    const int h = n >> 6;
    const int dq = n & 63;          // 8-col groups never straddle a head (64%8==0)
    const bool rope = (z < 2);

    #pragma unroll
    for (int i = 0; i < 8; i++) {
        const int gm = m0 + ty * 8 + i;
        const int bb = gm >> 11;           // /2048
        const int s  = gm & (SEQ - 1);
        if (rope) {
            #pragma unroll
            for (int c = 0; c < 8; c += 2) {
                const int fi = (dq + c) >> 1;               // 0..31
                const float inv = powf(10000.0f, -(float)fi * (1.0f / 32.0f));
                const float ang = (float)s * inv;
                float sn, cs;
                sincosf(ang, &sn, &cs);
                const float x1 = acc[i][c], x2 = acc[i][c + 1];
                acc[i][c]     = x1 * cs - x2 * sn;
                acc[i][c + 1] = x1 * sn + x2 * cs;
            }
        }
        float* dst = Out + (((size_t)(bb * NHEAD + h) * SEQ + s) * DHEAD + dq);
        *(float4*)(dst)     = make_float4(acc[i][0], acc[i][1], acc[i][2], acc[i][3]);
        *(float4*)(dst + 4) = make_float4(acc[i][4], acc[i][5], acc[i][6], acc[i][7]);
    }
}

__global__ __launch_bounds__(256) void out_gemm(const float* __restrict__ Wo,
                                                float* __restrict__ C)
{
    __shared__ float As[16][128];
    __shared__ float Bs[16][128];

    const int m0 = blockIdx.y * 128;
    const int n0 = blockIdx.x * 128;
    const int tid = threadIdx.x;
    const int tx = tid & 15, ty = tid >> 4;
    const int lr = tid >> 2;
    const int kc = (tid & 3) * 4;

    float acc[8][8];
    #pragma unroll
    for (int i = 0; i < 8; i++)
        #pragma unroll
        for (int j = 0; j < 8; j++) acc[i][j] = 0.0f;

    const float* Ap = g_A + (size_t)(m0 + lr) * DMODEL + kc;
    const float* Bp = Wo  + (size_t)(n0 + lr) * DMODEL + kc;

    for (int kt = 0; kt < DMODEL / 16; kt++) {
        float4 a0 = *(const float4*)(Ap);
        float4 a1 = *(const float4*)(Ap + (size_t)64 * DMODEL);
        float4 b0 = *(const float4*)(Bp);
        float4 b1 = *(const float4*)(Bp + (size_t)64 * DMODEL);
        Ap += 16; Bp += 16;

        __syncthreads();
        As[kc + 0][lr] = a0.x; As[kc + 1][lr] = a0.y;
        As[kc + 2][lr] = a0.z; As[kc + 3][lr] = a0.w;
        As[kc + 0][lr + 64] = a1.x; As[kc + 1][lr + 64] = a1.y;
        As[kc + 2][lr + 64] = a1.z; As[kc + 3][lr + 64] = a1.w;
        Bs[kc + 0][lr] = b0.x; Bs[kc + 1][lr] = b0.y;
        Bs[kc + 2][lr] = b0.z; Bs[kc + 3][lr] = b0.w;
        Bs[kc + 0][lr + 64] = b1.x; Bs[kc + 1][lr + 64] = b1.y;
        Bs[kc + 2][lr + 64] = b1.z; Bs[kc + 3][lr + 64] = b1.w;
        __syncthreads();

        #pragma unroll
        for (int k = 0; k < 16; k++) {
            float a[8], b[8];
            *(float4*)(a)     = *(float4*)&As[k][ty * 8];
            *(float4*)(a + 4) = *(float4*)&As[k][ty * 8 + 4];
            *(float4*)(b)     = *(float4*)&Bs[k][tx * 8];
            *(float4*)(b + 4) = *(float4*)&Bs[k][tx * 8 + 4];
            #pragma unroll
            for (int i = 0; i < 8; i++)
                #pragma unroll
                for (int j = 0; j < 8; j++)
                    acc[i][j] = fmaf(a[i], b[j], acc[i][j]);
        }
    }

    #pragma unroll
    for (int i = 0; i < 8; i++) {
        const int gm = m0 + ty * 8 + i;
        float* dst = C + (size_t)gm * DMODEL + n0 + tx * 8;
        *(float4*)(dst)     = make_float4(acc[i][0], acc[i][1], acc[i][2], acc[i][3]);
        *(float4*)(dst + 4) = make_float4(acc[i][4], acc[i][5], acc[i][6], acc[i][7]);
    }
}

// ---------------------------------------------------------------------------
// Flash attention, fp32. One block per (q-tile of 64, b*h). 256 threads as
// 16x16: score phase -> thread tile 4q x 4k; O phase -> 4q x 4d.
// Smem: Qs[d][q], Ks[d][k] (64x64 transposed), Vs[k][d], Ps[k][q] (stride 68).
// Online softmax stats reduced across tx via width-16 xor shuffles.
// ---------------------------------------------------------------------------
#define FLASH_SMEM_FLOATS (4096 * 3 + 64 * 68)   // 16640 floats = 66560 B

__global__ __launch_bounds__(256) void flash_kernel()
{
    extern __shared__ float sm[];
    float* Qs = sm;             // [64][64]  Qs[d*64+q]
    float* Ks = sm + 4096;      // [64][64]  Ks[d*64+k]
    float* Vs = sm + 8192;      // [64][64]  Vs[k*64+d]
    float* Ps = sm + 12288;     // [64][68]  Ps[k*68+q]

    const int qt = blockIdx.x;
    const int bh = blockIdx.y;
    const float* Qb = g_Q + (size_t)bh * SEQ * DHEAD;
    const float* Kb = g_K + (size_t)bh * SEQ * DHEAD;
    const float* Vb = g_V + (size_t)bh * SEQ * DHEAD;

    const int tid = threadIdx.x;
    const int tx = tid & 15, ty = tid >> 4;
    const int q0 = qt * 64;
    const int lr = tid >> 2;           // 0..63
    const int c0 = (tid & 3) * 4;      // 0,4,8,12

    // Load Q tile transposed, pre-scaled by 1/sqrt(64)
    #pragma unroll
    for (int j = 0; j < 4; j++) {
        const int col = c0 + j * 16;
        float4 v = *(const float4*)(Qb + (size_t)(q0 + lr) * DHEAD + col);
        Qs[(col + 0) * 64 + lr] = v.x * 0.125f;
        Qs[(col + 1) * 64 + lr] = v.y * 0.125f;
        Qs[(col + 2) * 64 + lr] = v.z * 0.125f;
        Qs[(col + 3) * 64 + lr] = v.w * 0.125f;
    }

    float m_i[4], l_i[4], acc[4][4];
    #pragma unroll
    for (int i = 0; i < 4; i++) {
        m_i[i] = -3.0e38f; l_i[i] = 0.0f;
        #pragma unroll
        for (int j = 0; j < 4; j++) acc[i][j] = 0.0f;
    }

    for (int kt = 0; kt <= qt; kt++) {
        const int k0 = kt * 64;
        __syncthreads();   // prev O-accum done (Vs/Ps free), Qs visible on iter 0
        #pragma unroll
        for (int j = 0; j < 4; j++) {
            const int col = c0 + j * 16;
            float4 kv = *(const float4*)(Kb + (size_t)(k0 + lr) * DHEAD + col);
            Ks[(col + 0) * 64 + lr] = kv.x;
            Ks[(col + 1) * 64 + lr] = kv.y;
            Ks[(col + 2) * 64 + lr] = kv.z;
            Ks[(col + 3) * 64 + lr] = kv.w;
            float4 vv = *(const float4*)(Vb + (size_t)(k0 + lr) * DHEAD + col);
            *(float4*)&Vs[lr * 64 + col] = vv;
        }
        __syncthreads();

        // S = Q @ K^T
        float s[4][4];
        #pragma unroll
        for (int i = 0; i < 4; i++)
            #pragma unroll
            for (int j = 0; j < 4; j++) s[i][j] = 0.0f;

        #pragma unroll 16
        for (int d = 0; d < 64; d++) {
            float4 qv = *(float4*)&Qs[d * 64 + ty * 4];
            float4 kv = *(float4*)&Ks[d * 64 + tx * 4];
            const float qa[4] = {qv.x, qv.y, qv.z, qv.w};
            const float ka[4] = {kv.x, kv.y, kv.z, kv.w};
            #pragma unroll
            for (int i = 0; i < 4; i++)
                #pragma unroll
                for (int j = 0; j < 4; j++)
                    s[i][j] = fmaf(qa[i], ka[j], s[i][j]);
        }

        // Causal mask (diagonal tile only)
        if (kt == qt) {
            #pragma unroll
            for (int i = 0; i < 4; i++)
                #pragma unroll
                for (int j = 0; j < 4; j++)
                    if (k0 + tx * 4 + j > q0 + ty * 4 + i) s[i][j] = -3.0e38f;
        }

        // Online softmax
        float alpha[4];
        #pragma unroll
        for (int i = 0; i < 4; i++) {
            float mx = fmaxf(fmaxf(s[i][0], s[i][1]), fmaxf(s[i][2], s[i][3]));
            #pragma unroll
            for (int off = 8; off > 0; off >>= 1)
                mx = fmaxf(mx, __shfl_xor_sync(0xffffffffu, mx, off, 16));
            const float mn = fmaxf(m_i[i], mx);
            alpha[i] = __expf(m_i[i] - mn);
            m_i[i] = mn;
        }
        #pragma unroll
        for (int i = 0; i < 4; i++) {
            float r = 0.0f;
            #pragma unroll
            for (int j = 0; j < 4; j++) {
                const float p = __expf(s[i][j] - m_i[i]);
                s[i][j] = p; r += p;
            }
            #pragma unroll
            for (int off = 8; off > 0; off >>= 1)
                r += __shfl_xor_sync(0xffffffffu, r, off, 16);
            l_i[i] = l_i[i] * alpha[i] + r;
            #pragma unroll
            for (int j = 0; j < 4; j++) acc[i][j] *= alpha[i];
        }

        // Stage P transposed: Ps[k][q]
        #pragma unroll
        for (int j = 0; j < 4; j++)
            *(float4*)&Ps[(tx * 4 + j) * 68 + ty * 4] =
                make_float4(s[0][j], s[1][j], s[2][j], s[3][j]);

        __syncthreads();

        // O += P @ V
        #pragma unroll 16
        for (int k = 0; k < 64; k++) {
            float4 pv = *(float4*)&Ps[k * 68 + ty * 4];
            float4 vv = *(float4*)&Vs[k * 64 + tx * 4];
            const float pa[4] = {pv.x, pv.y, pv.z, pv.w};
            const float va[4] = {vv.x, vv.y, vv.z, vv.w};
            #pragma unroll
            for (int i = 0; i < 4; i++)
                #pragma unroll
                for (int j = 0; j < 4; j++)
                    acc[i][j] = fmaf(pa[i], va[j], acc[i][j]);
        }
    }

    // Normalize + write to [b][s][h*64+d]
    const int b = bh >> 4, h = bh & 15;
    #pragma unroll
    for (int i = 0; i < 4; i++) {
        const float inv = 1.0f / l_i[i];
        const int gq = q0 + ty * 4 + i;
        float* dst = g_A + ((size_t)(b * SEQ + gq)) * DMODEL + h * DHEAD + tx * 4;
        *(float4*)dst = make_float4(acc[i][0] * inv, acc[i][1] * inv,
                                    acc[i][2] * inv, acc[i][3] * inv);
    }
}

// ---------------------------------------------------------------------------

extern "C" void kernel_launch(void* const* d_in, const int* in_sizes, int n_in,
                              void* d_out, int out_size)
{
    const float* x  = (const float*)d_in[0];
    const float* Wq = (const float*)d_in[1];
    const float* Wk = (const float*)d_in[2];
    const float* Wv = (const float*)d_in[3];
    const float* Wo = (const float*)d_in[4];
    float* out = (float*)d_out;

    cudaFuncSetAttribute(flash_kernel, cudaFuncAttributeMaxDynamicSharedMemorySize,
                         FLASH_SMEM_FLOATS * (int)sizeof(float));

    dim3 g1(DMODEL / 128, (BATCH * SEQ) / 128, 3);
    qkv_gemm<<<g1, 256>>>(x, Wq, Wk, Wv);

    flash_kernel<<<dim3(SEQ / 64, BATCH * NHEAD), 256,
                   FLASH_SMEM_FLOATS * (int)sizeof(float)>>>();

    dim3 g2(DMODEL / 128, (BATCH * SEQ) / 128, 1);
    out_gemm<<<g2, 256>>>(Wo, out);
}

// round 6
// speedup vs baseline: 1.0042x; 1.0042x over previous
#include <cuda_runtime.h>
#include <math.h>

// Problem constants (from setup_inputs): B=4, S=2048, D=1024, H=16, dh=64
#define BATCH 4
#define SEQ   2048
#define DMODEL 1024
#define NHEAD 16
#define DHEAD 64

// Scratch (alloc-free rule: __device__ globals)
__device__ float g_Q[(size_t)BATCH * NHEAD * SEQ * DHEAD]; // [b][h][s][d]
__device__ float g_K[(size_t)BATCH * NHEAD * SEQ * DHEAD];
__device__ float g_V[(size_t)BATCH * NHEAD * SEQ * DHEAD];
__device__ float g_A[(size_t)BATCH * SEQ * DMODEL];        // attn out, [b][s][h*64+d]

// ---------------------------------------------------------------------------
// GEMM: C[m][n] = sum_k X[m][k] * W[n][k]   (X: [8192,1024], W: [1024,1024])
// 128x128 block tile, BK=16, 256 threads, 8x8 per-thread register tile.
// MODE 0 (qkv): z selects Wq/Wk/Wv; epilogue applies RoPE (z<2) and writes
//               scratch in [b][h][s][dh] layout.
// MODE 1 (out): plain row-major store to output.
// ---------------------------------------------------------------------------

__global__ __launch_bounds__(256) void qkv_gemm(const float* __restrict__ X,
                                                const float* __restrict__ Wq,
                                                const float* __restrict__ Wk,
                                                const float* __restrict__ Wv)
{
    __shared__ float As[16][128];
    __shared__ float Bs[16][128];

    const int z = blockIdx.z;
    const float* W = (z == 0) ? Wq : ((z == 1) ? Wk : Wv);
    float* Out = (z == 0) ? g_Q : ((z == 1) ? g_K : g_V);

    const int m0 = blockIdx.y * 128;
    const int n0 = blockIdx.x * 128;
    const int tid = threadIdx.x;
    const int tx = tid & 15, ty = tid >> 4;
    const int lr = tid >> 2;            // 0..63
    const int kc = (tid & 3) * 4;       // 0,4,8,12

    float acc[8][8];
    #pragma unroll
    for (int i = 0; i < 8; i++)
        #pragma unroll
        for (int j = 0; j < 8; j++) acc[i][j] = 0.0f;

    const float* Ap = X + (size_t)(m0 + lr) * DMODEL + kc;
    const float* Bp = W + (size_t)(n0 + lr) * DMODEL + kc;

    for (int kt = 0; kt < DMODEL / 16; kt++) {
        float4 a0 = *(const float4*)(Ap);
        float4 a1 = *(const float4*)(Ap + (size_t)64 * DMODEL);
        float4 b0 = *(const float4*)(Bp);
        float4 b1 = *(const float4*)(Bp + (size_t)64 * DMODEL);
        Ap += 16; Bp += 16;

        __syncthreads();
        As[kc + 0][lr] = a0.x; As[kc + 1][lr] = a0.y;
        As[kc + 2][lr] = a0.z; As[kc + 3][lr] = a0.w;
        As[kc + 0][lr + 64] = a1.x; As[kc + 1][lr + 64] = a1.y;
        As[kc + 2][lr + 64] = a1.z; As[kc + 3][lr + 64] = a1.w;
        Bs[kc + 0][lr] = b0.x; Bs[kc + 1][lr] = b0.y;
        Bs[kc + 2][lr] = b0.z; Bs[kc + 3][lr] = b0.w;
        Bs[kc + 0][lr + 64] = b1.x; Bs[kc + 1][lr + 64] = b1.y;
        Bs[kc + 2][lr + 64] = b1.z; Bs[kc + 3][lr + 64] = b1.w;
        __syncthreads();

        #pragma unroll
        for (int k = 0; k < 16; k++) {
            float a[8], b[8];
            *(float4*)(a)     = *(float4*)&As[k][ty * 8];
            *(float4*)(a + 4) = *(float4*)&As[k][ty * 8 + 4];
            *(float4*)(b)     = *(float4*)&Bs[k][tx * 8];
            *(float4*)(b + 4) = *(float4*)&Bs[k][tx * 8 + 4];
            #pragma unroll
            for (int i = 0; i < 8; i++)
                #pragma unroll
                for (int j = 0; j < 8; j++)
                    acc[i][j] = fmaf(a[i], b[j], acc[i][j]);
        }
    }

    // Epilogue: RoPE (for Q,K) + scatter to [b][h][s][dh]
    const int n = n0 + tx * 8;
    const int h = n >> 6;
    const int dq = n & 63;          // 8-col groups never straddle a head (64%8==0)
    const bool rope = (z < 2);

    #pragma unroll
    for (int i = 0; i < 8; i++) {
        const int gm = m0 + ty * 8 + i;
        const int bb = gm >> 11;           // /2048
        const int s  = gm & (SEQ - 1);
        if (rope) {
            #pragma unroll
            for (int c = 0; c < 8; c += 2) {
                const int fi = (dq + c) >> 1;               // 0..31
                const float inv = powf(10000.0f, -(float)fi * (1.0f / 32.0f));
                const float ang = (float)s * inv;
                float sn, cs;
                sincosf(ang, &sn, &cs);
                const float x1 = acc[i][c], x2 = acc[i][c + 1];
                acc[i][c]     = x1 * cs - x2 * sn;
                acc[i][c + 1] = x1 * sn + x2 * cs;
            }
        }
        float* dst = Out + (((size_t)(bb * NHEAD + h) * SEQ + s) * DHEAD + dq);
        *(float4*)(dst)     = make_float4(acc[i][0], acc[i][1], acc[i][2], acc[i][3]);
        *(float4*)(dst + 4) = make_float4(acc[i][4], acc[i][5], acc[i][6], acc[i][7]);
    }
}

__global__ __launch_bounds__(256) void out_gemm(const float* __restrict__ Wo,
                                                float* __restrict__ C)
{
    __shared__ float As[16][128];
    __shared__ float Bs[16][128];

    const int m0 = blockIdx.y * 128;
    const int n0 = blockIdx.x * 128;
    const int tid = threadIdx.x;
    const int tx = tid & 15, ty = tid >> 4;
    const int lr = tid >> 2;
    const int kc = (tid & 3) * 4;

    float acc[8][8];
    #pragma unroll
    for (int i = 0; i < 8; i++)
        #pragma unroll
        for (int j = 0; j < 8; j++) acc[i][j] = 0.0f;

    const float* Ap = g_A + (size_t)(m0 + lr) * DMODEL + kc;
    const float* Bp = Wo  + (size_t)(n0 + lr) * DMODEL + kc;

    for (int kt = 0; kt < DMODEL / 16; kt++) {
        float4 a0 = *(const float4*)(Ap);
        float4 a1 = *(const float4*)(Ap + (size_t)64 * DMODEL);
        float4 b0 = *(const float4*)(Bp);
        float4 b1 = *(const float4*)(Bp + (size_t)64 * DMODEL);
        Ap += 16; Bp += 16;

        __syncthreads();
        As[kc + 0][lr] = a0.x; As[kc + 1][lr] = a0.y;
        As[kc + 2][lr] = a0.z; As[kc + 3][lr] = a0.w;
        As[kc + 0][lr + 64] = a1.x; As[kc + 1][lr + 64] = a1.y;
        As[kc + 2][lr + 64] = a1.z; As[kc + 3][lr + 64] = a1.w;
        Bs[kc + 0][lr] = b0.x; Bs[kc + 1][lr] = b0.y;
        Bs[kc + 2][lr] = b0.z; Bs[kc + 3][lr] = b0.w;
        Bs[kc + 0][lr + 64] = b1.x; Bs[kc + 1][lr + 64] = b1.y;
        Bs[kc + 2][lr + 64] = b1.z; Bs[kc + 3][lr + 64] = b1.w;
        __syncthreads();

        #pragma unroll
        for (int k = 0; k < 16; k++) {
            float a[8], b[8];
            *(float4*)(a)     = *(float4*)&As[k][ty * 8];
            *(float4*)(a + 4) = *(float4*)&As[k][ty * 8 + 4];
            *(float4*)(b)     = *(float4*)&Bs[k][tx * 8];
            *(float4*)(b + 4) = *(float4*)&Bs[k][tx * 8 + 4];
            #pragma unroll
            for (int i = 0; i < 8; i++)
                #pragma unroll
                for (int j = 0; j < 8; j++)
                    acc[i][j] = fmaf(a[i], b[j], acc[i][j]);
        }
    }

    #pragma unroll
    for (int i = 0; i < 8; i++) {
        const int gm = m0 + ty * 8 + i;
        float* dst = C + (size_t)gm * DMODEL + n0 + tx * 8;
        *(float4*)(dst)     = make_float4(acc[i][0], acc[i][1], acc[i][2], acc[i][3]);
        *(float4*)(dst + 4) = make_float4(acc[i][4], acc[i][5], acc[i][6], acc[i][7]);
    }
}

// ---------------------------------------------------------------------------
// Flash attention, fp32. One block per (q-tile of 64, b*h). 256 threads as
// 16x16: score phase -> thread tile 4q x 4k; O phase -> 4q x 4d.
// Smem: Qs[d][q], Ks[d][k] (64x64 transposed), Vs[k][d], Ps[k][q] (stride 68).
// Online softmax stats reduced across tx via width-16 xor shuffles.
// ---------------------------------------------------------------------------
#define FLASH_SMEM_FLOATS (4096 * 3 + 64 * 68)   // 16640 floats = 66560 B

__global__ __launch_bounds__(256) void flash_kernel()
{
    extern __shared__ float sm[];
    float* Qs = sm;             // [64][64]  Qs[d*64+q]
    float* Ks = sm + 4096;      // [64][64]  Ks[d*64+k]
    float* Vs = sm + 8192;      // [64][64]  Vs[k*64+d]
    float* Ps = sm + 12288;     // [64][68]  Ps[k*68+q]

    const int qt = blockIdx.x;
    const int bh = blockIdx.y;
    const float* Qb = g_Q + (size_t)bh * SEQ * DHEAD;
    const float* Kb = g_K + (size_t)bh * SEQ * DHEAD;
    const float* Vb = g_V + (size_t)bh * SEQ * DHEAD;

    const int tid = threadIdx.x;
    const int tx = tid & 15, ty = tid >> 4;
    const int q0 = qt * 64;
    const int lr = tid >> 2;           // 0..63
    const int c0 = (tid & 3) * 4;      // 0,4,8,12

    // Load Q tile transposed, pre-scaled by 1/sqrt(64)
    #pragma unroll
    for (int j = 0; j < 4; j++) {
        const int col = c0 + j * 16;
        float4 v = *(const float4*)(Qb + (size_t)(q0 + lr) * DHEAD + col);
        Qs[(col + 0) * 64 + lr] = v.x * 0.125f;
        Qs[(col + 1) * 64 + lr] = v.y * 0.125f;
        Qs[(col + 2) * 64 + lr] = v.z * 0.125f;
        Qs[(col + 3) * 64 + lr] = v.w * 0.125f;
    }

    float m_i[4], l_i[4], acc[4][4];
    #pragma unroll
    for (int i = 0; i < 4; i++) {
        m_i[i] = -3.0e38f; l_i[i] = 0.0f;
        #pragma unroll
        for (int j = 0; j < 4; j++) acc[i][j] = 0.0f;
    }

    for (int kt = 0; kt <= qt; kt++) {
        const int k0 = kt * 64;
        __syncthreads();   // prev O-accum done (Vs/Ps free), Qs visible on iter 0
        #pragma unroll
        for (int j = 0; j < 4; j++) {
            const int col = c0 + j * 16;
            float4 kv = *(const float4*)(Kb + (size_t)(k0 + lr) * DHEAD + col);
            Ks[(col + 0) * 64 + lr] = kv.x;
            Ks[(col + 1) * 64 + lr] = kv.y;
            Ks[(col + 2) * 64 + lr] = kv.z;
            Ks[(col + 3) * 64 + lr] = kv.w;
            float4 vv = *(const float4*)(Vb + (size_t)(k0 + lr) * DHEAD + col);
            *(float4*)&Vs[lr * 64 + col] = vv;
        }
        __syncthreads();

        // S = Q @ K^T
        float s[4][4];
        #pragma unroll
        for (int i = 0; i < 4; i++)
            #pragma unroll
            for (int j = 0; j < 4; j++) s[i][j] = 0.0f;

        #pragma unroll 16
        for (int d = 0; d < 64; d++) {
            float4 qv = *(float4*)&Qs[d * 64 + ty * 4];
            float4 kv = *(float4*)&Ks[d * 64 + tx * 4];
            const float qa[4] = {qv.x, qv.y, qv.z, qv.w};
            const float ka[4] = {kv.x, kv.y, kv.z, kv.w};
            #pragma unroll
            for (int i = 0; i < 4; i++)
                #pragma unroll
                for (int j = 0; j < 4; j++)
                    s[i][j] = fmaf(qa[i], ka[j], s[i][j]);
        }

        // Causal mask (diagonal tile only)
        if (kt == qt) {
            #pragma unroll
            for (int i = 0; i < 4; i++)
                #pragma unroll
                for (int j = 0; j < 4; j++)
                    if (k0 + tx * 4 + j > q0 + ty * 4 + i) s[i][j] = -3.0e38f;
        }

        // Online softmax
        float alpha[4];
        #pragma unroll
        for (int i = 0; i < 4; i++) {
            float mx = fmaxf(fmaxf(s[i][0], s[i][1]), fmaxf(s[i][2], s[i][3]));
            #pragma unroll
            for (int off = 8; off > 0; off >>= 1)
                mx = fmaxf(mx, __shfl_xor_sync(0xffffffffu, mx, off, 16));
            const float mn = fmaxf(m_i[i], mx);
            alpha[i] = __expf(m_i[i] - mn);
            m_i[i] = mn;
        }
        #pragma unroll
        for (int i = 0; i < 4; i++) {
            float r = 0.0f;
            #pragma unroll
            for (int j = 0; j < 4; j++) {
                const float p = __expf(s[i][j] - m_i[i]);
                s[i][j] = p; r += p;
            }
            #pragma unroll
            for (int off = 8; off > 0; off >>= 1)
                r += __shfl_xor_sync(0xffffffffu, r, off, 16);
            l_i[i] = l_i[i] * alpha[i] + r;
            #pragma unroll
            for (int j = 0; j < 4; j++) acc[i][j] *= alpha[i];
        }

        // Stage P transposed: Ps[k][q]
        #pragma unroll
        for (int j = 0; j < 4; j++)
            *(float4*)&Ps[(tx * 4 + j) * 68 + ty * 4] =
                make_float4(s[0][j], s[1][j], s[2][j], s[3][j]);

        __syncthreads();

        // O += P @ V
        #pragma unroll 16
        for (int k = 0; k < 64; k++) {
            float4 pv = *(float4*)&Ps[k * 68 + ty * 4];
            float4 vv = *(float4*)&Vs[k * 64 + tx * 4];
            const float pa[4] = {pv.x, pv.y, pv.z, pv.w};
            const float va[4] = {vv.x, vv.y, vv.z, vv.w};
            #pragma unroll
            for (int i = 0; i < 4; i++)
                #pragma unroll
                for (int j = 0; j < 4; j++)
                    acc[i][j] = fmaf(pa[i], va[j], acc[i][j]);
        }
    }

    // Normalize + write to [b][s][h*64+d]
    const int b = bh >> 4, h = bh & 15;
    #pragma unroll
    for (int i = 0; i < 4; i++) {
        const float inv = 1.0f / l_i[i];
        const int gq = q0 + ty * 4 + i;
        float* dst = g_A + ((size_t)(b * SEQ + gq)) * DMODEL + h * DHEAD + tx * 4;
        *(float4*)dst = make_float4(acc[i][0] * inv, acc[i][1] * inv,
                                    acc[i][2] * inv, acc[i][3] * inv);
    }
}

// ---------------------------------------------------------------------------

extern "C" void kernel_launch(void* const* d_in, const int* in_sizes, int n_in,
                              void* d_out, int out_size)
{
    const float* x  = (const float*)d_in[0];
    const float* Wq = (const float*)d_in[1];
    const float* Wk = (const float*)d_in[2];
    const float* Wv = (const float*)d_in[3];
    const float* Wo = (const float*)d_in[4];
    float* out = (float*)d_out;

    cudaFuncSetAttribute(flash_kernel, cudaFuncAttributeMaxDynamicSharedMemorySize,
                         FLASH_SMEM_FLOATS * (int)sizeof(float));

    dim3 g1(DMODEL / 128, (BATCH * SEQ) / 128, 3);
    qkv_gemm<<<g1, 256>>>(x, Wq, Wk, Wv);

    flash_kernel<<<dim3(SEQ / 64, BATCH * NHEAD), 256,
                   FLASH_SMEM_FLOATS * (int)sizeof(float)>>>();

    dim3 g2(DMODEL / 128, (BATCH * SEQ) / 128, 1);
    out_gemm<<<g2, 256>>>(Wo, out);
}

// round 8
// speedup vs baseline: 1.4737x; 1.4675x over previous
#include <cuda_runtime.h>
#include <stdint.h>
#include <math.h>

// Problem constants: B=4, S=2048, D=1024, H=16, dh=64
#define BATCH 4
#define SEQ   2048
#define DMODEL 1024
#define NHEAD 16
#define DHEAD 64

// Scratch (alloc-free rule: __device__ globals)
__device__ float g_Q[(size_t)BATCH * NHEAD * SEQ * DHEAD]; // [b][h][s][d]
__device__ float g_K[(size_t)BATCH * NHEAD * SEQ * DHEAD];
__device__ float g_V[(size_t)BATCH * NHEAD * SEQ * DHEAD];
__device__ float g_A[(size_t)BATCH * SEQ * DMODEL];        // attn out [b][s][h*64+d]

// ---------------------------------------------------------------------------
// TF32 tensor-core GEMM:  C[m][n] = sum_k A[m][k] * W[n][k]
// M=8192, N=1024, K=1024. 128x128 block tile, BK=32, 8 warps (2m x 4n),
// warp tile 64x32 via mma.sync.m16n8k8.tf32. cp.async double-buffered smem,
// XOR-swizzled fp32 tiles, cvt->tf32 at fragment load.
// MODE 0: z in {0,1,2} selects Wq/Wk/Wv; epilogue fuses RoPE (z<2) and
//         scatters to [b][h][s][dh]. MODE 1: plain row-major store.
// ---------------------------------------------------------------------------

__device__ __forceinline__ void cp16(uint32_t dst, const void* src) {
    asm volatile("cp.async.cg.shared.global [%0], [%1], 16;" :: "r"(dst), "l"(src));
}

__device__ __forceinline__ uint32_t ldcvt(const float* S, int m, int k) {
    float v = S[m * 32 + (((k >> 2) ^ (m & 7)) << 2) + (k & 3)];
    uint32_t r;
    asm("cvt.rna.tf32.f32 %0, %1;" : "=r"(r) : "f"(v));
    return r;
}

__device__ __forceinline__ void mma_tf32(float c[4], const uint32_t a[4],
                                         const uint32_t b[2]) {
    asm volatile(
        "mma.sync.aligned.m16n8k8.row.col.f32.tf32.tf32.f32 "
        "{%0,%1,%2,%3}, {%4,%5,%6,%7}, {%8,%9}, {%0,%1,%2,%3};"
        : "+f"(c[0]), "+f"(c[1]), "+f"(c[2]), "+f"(c[3])
        : "r"(a[0]), "r"(a[1]), "r"(a[2]), "r"(a[3]), "r"(b[0]), "r"(b[1]));
}

template <int MODE>
__global__ __launch_bounds__(256) void gemm_tf32(
    const float* __restrict__ A,
    const float* __restrict__ W0,
    const float* __restrict__ W1,
    const float* __restrict__ W2,
    float* __restrict__ Cout)
{
    extern __shared__ float gsm[];          // 16384 floats = 64KB (2x(A+B))
    const int z = (MODE == 0) ? blockIdx.z : 0;
    const float* Ain = (MODE == 0) ? A : g_A;
    const float* W = (MODE == 0) ? ((z == 0) ? W0 : (z == 1) ? W1 : W2) : W0;
    float* Out = (MODE == 0) ? ((z == 0) ? g_Q : (z == 1) ? g_K : g_V) : Cout;

    const int m0 = blockIdx.y * 128, n0 = blockIdx.x * 128;
    const int t = threadIdx.x;
    const int lane = t & 31, wid = t >> 5;
    const int wm = wid >> 2, wn = wid & 3;      // 2 x 4 warp grid
    const int gi = lane >> 2, ti = lane & 3;

    float* Ab[2] = {gsm, gsm + 8192};
    float* Bb[2] = {gsm + 4096, gsm + 12288};
    uint32_t sb;
    asm("{ .reg .u64 u; cvta.to.shared.u64 u, %1; cvt.u32.u64 %0, u; }"
        : "=r"(sb) : "l"(gsm));
    const uint32_t aoff0 = sb, aoff1 = sb + 8192 * 4;
    const uint32_t boff0 = sb + 4096 * 4, boff1 = sb + 12288 * 4;

    const int rr = t >> 3, cg = t & 7;          // load row 0..31, float4 group
    const float* Ag = Ain + (size_t)(m0 + rr) * DMODEL + cg * 4;
    const float* Bg = W + (size_t)(n0 + rr) * DMODEL + cg * 4;
    const int dsw = ((cg ^ (rr & 7)) << 2);     // (r&7)==(rr&7) for r=rr+32i

    float acc[4][4][4];
    #pragma unroll
    for (int mi = 0; mi < 4; mi++)
        #pragma unroll
        for (int ni = 0; ni < 4; ni++)
            #pragma unroll
            for (int c = 0; c < 4; c++) acc[mi][ni][c] = 0.0f;

    auto stage = [&](int buf, int kt) {
        const float* ag = Ag + kt * 32;
        const float* bg = Bg + kt * 32;
        uint32_t ad = (buf ? aoff1 : aoff0) + (rr * 32 + dsw) * 4;
        uint32_t bd = (buf ? boff1 : boff0) + (rr * 32 + dsw) * 4;
        #pragma unroll
        for (int i = 0; i < 4; i++) {
            cp16(ad + i * 4096, ag + (size_t)i * 32 * DMODEL);
            cp16(bd + i * 4096, bg + (size_t)i * 32 * DMODEL);
        }
        asm volatile("cp.async.commit_group;");
    };

    stage(0, 0);
    for (int kt = 0; kt < DMODEL / 32; kt++) {
        const int buf = kt & 1;
        asm volatile("cp.async.wait_group 0;");
        __syncthreads();
        if (kt < DMODEL / 32 - 1) stage(buf ^ 1, kt + 1);

        const float* Sa = Ab[buf];
        const float* Sb = Bb[buf];
        #pragma unroll
        for (int ks = 0; ks < 4; ks++) {
            const int kk = ks * 8 + ti;
            uint32_t af[4][4];
            #pragma unroll
            for (int mi = 0; mi < 4; mi++) {
                const int m = wm * 64 + mi * 16 + gi;
                af[mi][0] = ldcvt(Sa, m, kk);
                af[mi][1] = ldcvt(Sa, m + 8, kk);
                af[mi][2] = ldcvt(Sa, m, kk + 4);
                af[mi][3] = ldcvt(Sa, m + 8, kk + 4);
            }
            uint32_t bf[4][2];
            #pragma unroll
            for (int ni = 0; ni < 4; ni++) {
                const int n = wn * 32 + ni * 8 + gi;
                bf[ni][0] = ldcvt(Sb, n, kk);
                bf[ni][1] = ldcvt(Sb, n, kk + 4);
            }
            #pragma unroll
            for (int mi = 0; mi < 4; mi++)
                #pragma unroll
                for (int ni = 0; ni < 4; ni++)
                    mma_tf32(acc[mi][ni], af[mi], bf[ni]);
        }
    }

    // Epilogue. C fragment: c0=(r, c), c1=(r, c+1), c2=(r+8, c), c3=(r+8, c+1)
    // with r = mi*16 + gi, c = ni*8 + 2*ti (even) -> adjacent even/odd pair.
    #pragma unroll
    for (int mi = 0; mi < 4; mi++) {
        #pragma unroll
        for (int ni = 0; ni < 4; ni++) {
            const int row = m0 + wm * 64 + mi * 16 + gi;
            const int col = n0 + wn * 32 + ni * 8 + 2 * ti;
            const float c0 = acc[mi][ni][0], c1 = acc[mi][ni][1];
            const float c2 = acc[mi][ni][2], c3 = acc[mi][ni][3];
            if (MODE == 1) {
                *(float2*)(Out + (size_t)row * DMODEL + col) = make_float2(c0, c1);
                *(float2*)(Out + (size_t)(row + 8) * DMODEL + col) = make_float2(c2, c3);
            } else {
                const int h = col >> 6, dq = col & 63;
                const int s0 = row & (SEQ - 1), bb = row >> 11;
                float* d0 = Out + (((size_t)(bb * NHEAD + h) * SEQ + s0) * DHEAD + dq);
                float* d1 = d0 + 8 * DHEAD;     // row+8 stays in same (b,h)
                if (z < 2) {
                    const int fi = dq >> 1;
                    const float inv = exp2f(-0.41524101186092356f * (float)fi);
                    float sn, cs;
                    sincosf((float)s0 * inv, &sn, &cs);
                    *(float2*)d0 = make_float2(c0 * cs - c1 * sn, c0 * sn + c1 * cs);
                    sincosf((float)(s0 + 8) * inv, &sn, &cs);
                    *(float2*)d1 = make_float2(c2 * cs - c3 * sn, c2 * sn + c3 * cs);
                } else {
                    *(float2*)d0 = make_float2(c0, c1);
                    *(float2*)d1 = make_float2(c2, c3);
                }
            }
        }
    }
}

// ---------------------------------------------------------------------------
// Flash attention, fp32 (unchanged this round). One block per (64-q tile, b*h).
// ---------------------------------------------------------------------------
#define FLASH_SMEM_FLOATS (4096 * 3 + 64 * 68)   // 66560 B

__global__ __launch_bounds__(256) void flash_kernel()
{
    extern __shared__ float sm[];
    float* Qs = sm;             // [64][64]  Qs[d*64+q]
    float* Ks = sm + 4096;      // [64][64]  Ks[d*64+k]
    float* Vs = sm + 8192;      // [64][64]  Vs[k*64+d]
    float* Ps = sm + 12288;     // [64][68]  Ps[k*68+q]

    const int qt = blockIdx.x;
    const int bh = blockIdx.y;
    const float* Qb = g_Q + (size_t)bh * SEQ * DHEAD;
    const float* Kb = g_K + (size_t)bh * SEQ * DHEAD;
    const float* Vb = g_V + (size_t)bh * SEQ * DHEAD;

    const int tid = threadIdx.x;
    const int tx = tid & 15, ty = tid >> 4;
    const int q0 = qt * 64;
    const int lr = tid >> 2;
    const int c0 = (tid & 3) * 4;

    #pragma unroll
    for (int j = 0; j < 4; j++) {
        const int col = c0 + j * 16;
        float4 v = *(const float4*)(Qb + (size_t)(q0 + lr) * DHEAD + col);
        Qs[(col + 0) * 64 + lr] = v.x * 0.125f;
        Qs[(col + 1) * 64 + lr] = v.y * 0.125f;
        Qs[(col + 2) * 64 + lr] = v.z * 0.125f;
        Qs[(col + 3) * 64 + lr] = v.w * 0.125f;
    }

    float m_i[4], l_i[4], acc[4][4];
    #pragma unroll
    for (int i = 0; i < 4; i++) {
        m_i[i] = -3.0e38f; l_i[i] = 0.0f;
        #pragma unroll
        for (int j = 0; j < 4; j++) acc[i][j] = 0.0f;
    }

    for (int kt = 0; kt <= qt; kt++) {
        const int k0 = kt * 64;
        __syncthreads();
        #pragma unroll
        for (int j = 0; j < 4; j++) {
            const int col = c0 + j * 16;
            float4 kv = *(const float4*)(Kb + (size_t)(k0 + lr) * DHEAD + col);
            Ks[(col + 0) * 64 + lr] = kv.x;
            Ks[(col + 1) * 64 + lr] = kv.y;
            Ks[(col + 2) * 64 + lr] = kv.z;
            Ks[(col + 3) * 64 + lr] = kv.w;
            float4 vv = *(const float4*)(Vb + (size_t)(k0 + lr) * DHEAD + col);
            *(float4*)&Vs[lr * 64 + col] = vv;
        }
        __syncthreads();

        float s[4][4];
        #pragma unroll
        for (int i = 0; i < 4; i++)
            #pragma unroll
            for (int j = 0; j < 4; j++) s[i][j] = 0.0f;

        #pragma unroll 16
        for (int d = 0; d < 64; d++) {
            float4 qv = *(float4*)&Qs[d * 64 + ty * 4];
            float4 kv = *(float4*)&Ks[d * 64 + tx * 4];
            const float qa[4] = {qv.x, qv.y, qv.z, qv.w};
            const float ka[4] = {kv.x, kv.y, kv.z, kv.w};
            #pragma unroll
            for (int i = 0; i < 4; i++)
                #pragma unroll
                for (int j = 0; j < 4; j++)
                    s[i][j] = fmaf(qa[i], ka[j], s[i][j]);
        }

        if (kt == qt) {
            #pragma unroll
            for (int i = 0; i < 4; i++)
                #pragma unroll
                for (int j = 0; j < 4; j++)
                    if (k0 + tx * 4 + j > q0 + ty * 4 + i) s[i][j] = -3.0e38f;
        }

        float alpha[4];
        #pragma unroll
        for (int i = 0; i < 4; i++) {
            float mx = fmaxf(fmaxf(s[i][0], s[i][1]), fmaxf(s[i][2], s[i][3]));
            #pragma unroll
            for (int off = 8; off > 0; off >>= 1)
                mx = fmaxf(mx, __shfl_xor_sync(0xffffffffu, mx, off, 16));
            const float mn = fmaxf(m_i[i], mx);
            alpha[i] = __expf(m_i[i] - mn);
            m_i[i] = mn;
        }
        #pragma unroll
        for (int i = 0; i < 4; i++) {
            float r = 0.0f;
            #pragma unroll
            for (int j = 0; j < 4; j++) {
                const float p = __expf(s[i][j] - m_i[i]);
                s[i][j] = p; r += p;
            }
            #pragma unroll
            for (int off = 8; off > 0; off >>= 1)
                r += __shfl_xor_sync(0xffffffffu, r, off, 16);
            l_i[i] = l_i[i] * alpha[i] + r;
            #pragma unroll
            for (int j = 0; j < 4; j++) acc[i][j] *= alpha[i];
        }

        #pragma unroll
        for (int j = 0; j < 4; j++)
            *(float4*)&Ps[(tx * 4 + j) * 68 + ty * 4] =
                make_float4(s[0][j], s[1][j], s[2][j], s[3][j]);

        __syncthreads();

        #pragma unroll 16
        for (int k = 0; k < 64; k++) {
            float4 pv = *(float4*)&Ps[k * 68 + ty * 4];
            float4 vv = *(float4*)&Vs[k * 64 + tx * 4];
            const float pa[4] = {pv.x, pv.y, pv.z, pv.w};
            const float va[4] = {vv.x, vv.y, vv.z, vv.w};
            #pragma unroll
            for (int i = 0; i < 4; i++)
                #pragma unroll
                for (int j = 0; j < 4; j++)
                    acc[i][j] = fmaf(pa[i], va[j], acc[i][j]);
        }
    }

    const int b = bh >> 4, h = bh & 15;
    #pragma unroll
    for (int i = 0; i < 4; i++) {
        const float inv = 1.0f / l_i[i];
        const int gq = q0 + ty * 4 + i;
        float* dst = g_A + ((size_t)(b * SEQ + gq)) * DMODEL + h * DHEAD + tx * 4;
        *(float4*)dst = make_float4(acc[i][0] * inv, acc[i][1] * inv,
                                    acc[i][2] * inv, acc[i][3] * inv);
    }
}

// ---------------------------------------------------------------------------

extern "C" void kernel_launch(void* const* d_in, const int* in_sizes, int n_in,
                              void* d_out, int out_size)
{
    const float* x  = (const float*)d_in[0];
    const float* Wq = (const float*)d_in[1];
    const float* Wk = (const float*)d_in[2];
    const float* Wv = (const float*)d_in[3];
    const float* Wo = (const float*)d_in[4];
    float* out = (float*)d_out;

    cudaFuncSetAttribute(gemm_tf32<0>, cudaFuncAttributeMaxDynamicSharedMemorySize, 65536);
    cudaFuncSetAttribute(gemm_tf32<1>, cudaFuncAttributeMaxDynamicSharedMemorySize, 65536);
    cudaFuncSetAttribute(flash_kernel, cudaFuncAttributeMaxDynamicSharedMemorySize,
                         FLASH_SMEM_FLOATS * (int)sizeof(float));

    dim3 g1(DMODEL / 128, (BATCH * SEQ) / 128, 3);
    gemm_tf32<0><<<g1, 256, 65536>>>(x, Wq, Wk, Wv, nullptr);

    flash_kernel<<<dim3(SEQ / 64, BATCH * NHEAD), 256,
                   FLASH_SMEM_FLOATS * (int)sizeof(float)>>>();

    dim3 g2(DMODEL / 128, (BATCH * SEQ) / 128, 1);
    gemm_tf32<1><<<g2, 256, 65536>>>(x, Wo, nullptr, nullptr, out);
}

// round 9
// speedup vs baseline: 2.3607x; 1.6019x over previous
#include <cuda_runtime.h>
#include <stdint.h>
#include <math.h>

// Problem constants: B=4, S=2048, D=1024, H=16, dh=64
#define BATCH 4
#define SEQ   2048
#define DMODEL 1024
#define NHEAD 16
#define DHEAD 64

// Scratch (alloc-free rule: __device__ globals)
__device__ float g_Q[(size_t)BATCH * NHEAD * SEQ * DHEAD]; // [b][h][s][d]
__device__ float g_K[(size_t)BATCH * NHEAD * SEQ * DHEAD];
__device__ float g_V[(size_t)BATCH * NHEAD * SEQ * DHEAD];
__device__ float g_A[(size_t)BATCH * SEQ * DMODEL];        // attn out [b][s][h*64+d]

// ---------------------------------------------------------------------------
// Shared TF32 MMA helpers (fragment layouts validated by passing R8 GEMM)
// ---------------------------------------------------------------------------
__device__ __forceinline__ void cp16(uint32_t dst, const void* src) {
    asm volatile("cp.async.cg.shared.global [%0], [%1], 16;" :: "r"(dst), "l"(src));
}

__device__ __forceinline__ uint32_t ldcvt(const float* S, int m, int k) {
    float v = S[m * 32 + (((k >> 2) ^ (m & 7)) << 2) + (k & 3)];
    uint32_t r;
    asm("cvt.rna.tf32.f32 %0, %1;" : "=r"(r) : "f"(v));
    return r;
}

__device__ __forceinline__ float tf32r(float x) {
    uint32_t u;
    asm("cvt.rna.tf32.f32 %0, %1;" : "=r"(u) : "f"(x));
    return __uint_as_float(u);
}

__device__ __forceinline__ void mma_tf32(float c[4], const uint32_t a[4],
                                         const uint32_t b[2]) {
    asm volatile(
        "mma.sync.aligned.m16n8k8.row.col.f32.tf32.tf32.f32 "
        "{%0,%1,%2,%3}, {%4,%5,%6,%7}, {%8,%9}, {%0,%1,%2,%3};"
        : "+f"(c[0]), "+f"(c[1]), "+f"(c[2]), "+f"(c[3])
        : "r"(a[0]), "r"(a[1]), "r"(a[2]), "r"(a[3]), "r"(b[0]), "r"(b[1]));
}

// ---------------------------------------------------------------------------
// TF32 tensor-core GEMM (unchanged from R8):  C[m][n] = sum_k A[m][k] * W[n][k]
// ---------------------------------------------------------------------------
template <int MODE>
__global__ __launch_bounds__(256) void gemm_tf32(
    const float* __restrict__ A,
    const float* __restrict__ W0,
    const float* __restrict__ W1,
    const float* __restrict__ W2,
    float* __restrict__ Cout)
{
    extern __shared__ float gsm[];          // 64KB: 2x(A 128x32 + B 128x32)
    const int z = (MODE == 0) ? blockIdx.z : 0;
    const float* Ain = (MODE == 0) ? A : g_A;
    const float* W = (MODE == 0) ? ((z == 0) ? W0 : (z == 1) ? W1 : W2) : W0;
    float* Out = (MODE == 0) ? ((z == 0) ? g_Q : (z == 1) ? g_K : g_V) : Cout;

    const int m0 = blockIdx.y * 128, n0 = blockIdx.x * 128;
    const int t = threadIdx.x;
    const int lane = t & 31, wid = t >> 5;
    const int wm = wid >> 2, wn = wid & 3;
    const int gi = lane >> 2, ti = lane & 3;

    float* Ab[2] = {gsm, gsm + 8192};
    float* Bb[2] = {gsm + 4096, gsm + 12288};
    uint32_t sb;
    asm("{ .reg .u64 u; cvta.to.shared.u64 u, %1; cvt.u32.u64 %0, u; }"
        : "=r"(sb) : "l"(gsm));
    const uint32_t aoff0 = sb, aoff1 = sb + 8192 * 4;
    const uint32_t boff0 = sb + 4096 * 4, boff1 = sb + 12288 * 4;

    const int rr = t >> 3, cg = t & 7;
    const float* Ag = Ain + (size_t)(m0 + rr) * DMODEL + cg * 4;
    const float* Bg = W + (size_t)(n0 + rr) * DMODEL + cg * 4;
    const int dsw = ((cg ^ (rr & 7)) << 2);

    float acc[4][4][4];
    #pragma unroll
    for (int mi = 0; mi < 4; mi++)
        #pragma unroll
        for (int ni = 0; ni < 4; ni++)
            #pragma unroll
            for (int c = 0; c < 4; c++) acc[mi][ni][c] = 0.0f;

    auto stage = [&](int buf, int kt) {
        const float* ag = Ag + kt * 32;
        const float* bg = Bg + kt * 32;
        uint32_t ad = (buf ? aoff1 : aoff0) + (rr * 32 + dsw) * 4;
        uint32_t bd = (buf ? boff1 : boff0) + (rr * 32 + dsw) * 4;
        #pragma unroll
        for (int i = 0; i < 4; i++) {
            cp16(ad + i * 4096, ag + (size_t)i * 32 * DMODEL);
            cp16(bd + i * 4096, bg + (size_t)i * 32 * DMODEL);
        }
        asm volatile("cp.async.commit_group;");
    };

    stage(0, 0);
    for (int kt = 0; kt < DMODEL / 32; kt++) {
        const int buf = kt & 1;
        asm volatile("cp.async.wait_group 0;");
        __syncthreads();
        if (kt < DMODEL / 32 - 1) stage(buf ^ 1, kt + 1);

        const float* Sa = Ab[buf];
        const float* Sb = Bb[buf];
        #pragma unroll
        for (int ks = 0; ks < 4; ks++) {
            const int kk = ks * 8 + ti;
            uint32_t af[4][4];
            #pragma unroll
            for (int mi = 0; mi < 4; mi++) {
                const int m = wm * 64 + mi * 16 + gi;
                af[mi][0] = ldcvt(Sa, m, kk);
                af[mi][1] = ldcvt(Sa, m + 8, kk);
                af[mi][2] = ldcvt(Sa, m, kk + 4);
                af[mi][3] = ldcvt(Sa, m + 8, kk + 4);
            }
            uint32_t bf[4][2];
            #pragma unroll
            for (int ni = 0; ni < 4; ni++) {
                const int n = wn * 32 + ni * 8 + gi;
                bf[ni][0] = ldcvt(Sb, n, kk);
                bf[ni][1] = ldcvt(Sb, n, kk + 4);
            }
            #pragma unroll
            for (int mi = 0; mi < 4; mi++)
                #pragma unroll
                for (int ni = 0; ni < 4; ni++)
                    mma_tf32(acc[mi][ni], af[mi], bf[ni]);
        }
    }

    #pragma unroll
    for (int mi = 0; mi < 4; mi++) {
        #pragma unroll
        for (int ni = 0; ni < 4; ni++) {
            const int row = m0 + wm * 64 + mi * 16 + gi;
            const int col = n0 + wn * 32 + ni * 8 + 2 * ti;
            const float c0 = acc[mi][ni][0], c1 = acc[mi][ni][1];
            const float c2 = acc[mi][ni][2], c3 = acc[mi][ni][3];
            if (MODE == 1) {
                *(float2*)(Out + (size_t)row * DMODEL + col) = make_float2(c0, c1);
                *(float2*)(Out + (size_t)(row + 8) * DMODEL + col) = make_float2(c2, c3);
            } else {
                const int h = col >> 6, dq = col & 63;
                const int s0 = row & (SEQ - 1), bb = row >> 11;
                float* d0 = Out + (((size_t)(bb * NHEAD + h) * SEQ + s0) * DHEAD + dq);
                float* d1 = d0 + 8 * DHEAD;
                if (z < 2) {
                    const int fi = dq >> 1;
                    const float inv = exp2f(-0.41524101186092356f * (float)fi);
                    float sn, cs;
                    sincosf((float)s0 * inv, &sn, &cs);
                    *(float2*)d0 = make_float2(c0 * cs - c1 * sn, c0 * sn + c1 * cs);
                    sincosf((float)(s0 + 8) * inv, &sn, &cs);
                    *(float2*)d1 = make_float2(c2 * cs - c3 * sn, c2 * sn + c3 * cs);
                } else {
                    *(float2*)d0 = make_float2(c0, c1);
                    *(float2*)d1 = make_float2(c2, c3);
                }
            }
        }
    }
}

// ---------------------------------------------------------------------------
// Tensor-core flash attention (tf32). BQ=128 (8 warps x 16 q-rows), BK=64.
// Q/K/V pre-rounded to tf32 at smem store. Pads: Q/K/P rows 68, V rows 72
// (conflict-free fragment LDS for both S=QK^T and O+=P@V operand patterns).
// Softmax on C-fragments in registers, quad shuffles (xor 1,2).
// P staged per-warp through smem (syncwarp only) into A-fragment layout.
// ---------------------------------------------------------------------------
#define FBQ 128
#define FBK 64
#define PADK 68
#define PADV 72
// floats: Qs 128*68 + Ks 64*68 + Vs 64*72 + Ps 8*16*68
#define FLASH_SMEM_FLOATS (128*PADK + 64*PADK + 64*PADV + 8*16*PADK)

__global__ __launch_bounds__(256, 2) void flash_tc()
{
    extern __shared__ float sm[];
    float* Qs = sm;                          // [128][68]
    float* Ks = Qs + 128 * PADK;             // [64][68]
    float* Vs = Ks + 64 * PADK;              // [64][72]
    float* Ps = Vs + 64 * PADV;              // [8][16][68]

    const int qt = (int)gridDim.x - 1 - (int)blockIdx.x;   // heavy blocks first
    const int bh = blockIdx.y;
    const float* Qb = g_Q + (size_t)bh * SEQ * DHEAD;
    const float* Kb = g_K + (size_t)bh * SEQ * DHEAD;
    const float* Vb = g_V + (size_t)bh * SEQ * DHEAD;

    const int tid = threadIdx.x;
    const int lane = tid & 31, w = tid >> 5;
    const int gi = lane >> 2, ti = lane & 3;
    const int q0 = qt * FBQ;
    const int wq0 = q0 + w * 16;
    float* Pw = Ps + w * 16 * PADK;

    // Load Q tile (scaled 1/8, tf32-rounded)
    {
        const int r = tid >> 1;
        const int cb = (tid & 1) * 32;
        #pragma unroll
        for (int j = 0; j < 8; j++) {
            float4 v = *(const float4*)(Qb + (size_t)(q0 + r) * DHEAD + cb + j * 4);
            float4 o = make_float4(tf32r(v.x * 0.125f), tf32r(v.y * 0.125f),
                                   tf32r(v.z * 0.125f), tf32r(v.w * 0.125f));
            *(float4*)&Qs[r * PADK + cb + j * 4] = o;
        }
    }

    float oacc[8][4];
    #pragma unroll
    for (int nt = 0; nt < 8; nt++)
        #pragma unroll
        for (int c = 0; c < 4; c++) oacc[nt][c] = 0.0f;
    float m0 = -1e30f, m1 = -1e30f, l0 = 0.0f, l1 = 0.0f;

    const int nkt = 2 * (qt + 1);
    for (int kt = 0; kt < nkt; kt++) {
        const int k0 = kt * FBK;
        __syncthreads();    // prev PV readers of Vs done; also Qs visibility on kt=0
        {
            const int r = tid >> 2;
            const int cb = (tid & 3) * 16;
            #pragma unroll
            for (int j = 0; j < 4; j++) {
                float4 kv = *(const float4*)(Kb + (size_t)(k0 + r) * DHEAD + cb + j * 4);
                *(float4*)&Ks[r * PADK + cb + j * 4] =
                    make_float4(tf32r(kv.x), tf32r(kv.y), tf32r(kv.z), tf32r(kv.w));
                float4 vv = *(const float4*)(Vb + (size_t)(k0 + r) * DHEAD + cb + j * 4);
                *(float4*)&Vs[r * PADV + cb + j * 4] =
                    make_float4(tf32r(vv.x), tf32r(vv.y), tf32r(vv.z), tf32r(vv.w));
            }
        }
        __syncthreads();

        // S = Q @ K^T  (16 x 64 per warp)
        float sfr[8][4];
        #pragma unroll
        for (int nt = 0; nt < 8; nt++)
            #pragma unroll
            for (int c = 0; c < 4; c++) sfr[nt][c] = 0.0f;

        #pragma unroll
        for (int kc = 0; kc < 8; kc++) {
            const int kk = kc * 8 + ti;
            uint32_t af[4];
            af[0] = __float_as_uint(Qs[(w * 16 + gi) * PADK + kk]);
            af[1] = __float_as_uint(Qs[(w * 16 + gi + 8) * PADK + kk]);
            af[2] = __float_as_uint(Qs[(w * 16 + gi) * PADK + kk + 4]);
            af[3] = __float_as_uint(Qs[(w * 16 + gi + 8) * PADK + kk + 4]);
            #pragma unroll
            for (int nt = 0; nt < 8; nt++) {
                uint32_t bf[2];
                bf[0] = __float_as_uint(Ks[(nt * 8 + gi) * PADK + kk]);
                bf[1] = __float_as_uint(Ks[(nt * 8 + gi) * PADK + kk + 4]);
                mma_tf32(sfr[nt], af, bf);
            }
        }

        // Causal mask (only tiles that cross the diagonal for this warp)
        if (k0 + FBK - 1 > wq0) {
            const int r0 = wq0 + gi, r1 = wq0 + gi + 8;
            #pragma unroll
            for (int nt = 0; nt < 8; nt++) {
                const int col = k0 + nt * 8 + 2 * ti;
                if (col > r0)     sfr[nt][0] = -1e30f;
                if (col + 1 > r0) sfr[nt][1] = -1e30f;
                if (col > r1)     sfr[nt][2] = -1e30f;
                if (col + 1 > r1) sfr[nt][3] = -1e30f;
            }
        }

        // Online softmax (rows gi and gi+8; columns spread over quad ti)
        float mx0 = -1e30f, mx1 = -1e30f;
        #pragma unroll
        for (int nt = 0; nt < 8; nt++) {
            mx0 = fmaxf(mx0, fmaxf(sfr[nt][0], sfr[nt][1]));
            mx1 = fmaxf(mx1, fmaxf(sfr[nt][2], sfr[nt][3]));
        }
        #pragma unroll
        for (int off = 1; off < 4; off <<= 1) {
            mx0 = fmaxf(mx0, __shfl_xor_sync(0xffffffffu, mx0, off));
            mx1 = fmaxf(mx1, __shfl_xor_sync(0xffffffffu, mx1, off));
        }
        const float mn0 = fmaxf(m0, mx0), mn1 = fmaxf(m1, mx1);
        const float al0 = __expf(m0 - mn0), al1 = __expf(m1 - mn1);
        m0 = mn0; m1 = mn1;

        float s0 = 0.0f, s1 = 0.0f;
        #pragma unroll
        for (int nt = 0; nt < 8; nt++) {
            sfr[nt][0] = __expf(sfr[nt][0] - mn0);
            sfr[nt][1] = __expf(sfr[nt][1] - mn0);
            sfr[nt][2] = __expf(sfr[nt][2] - mn1);
            sfr[nt][3] = __expf(sfr[nt][3] - mn1);
            s0 += sfr[nt][0] + sfr[nt][1];
            s1 += sfr[nt][2] + sfr[nt][3];
        }
        #pragma unroll
        for (int off = 1; off < 4; off <<= 1) {
            s0 += __shfl_xor_sync(0xffffffffu, s0, off);
            s1 += __shfl_xor_sync(0xffffffffu, s1, off);
        }
        l0 = l0 * al0 + s0;
        l1 = l1 * al1 + s1;
        #pragma unroll
        for (int nt = 0; nt < 8; nt++) {
            oacc[nt][0] *= al0; oacc[nt][1] *= al0;
            oacc[nt][2] *= al1; oacc[nt][3] *= al1;
        }

        // Stage P (tf32-rounded) into per-warp smem, A-fragment layout
        #pragma unroll
        for (int nt = 0; nt < 8; nt++) {
            *(float2*)&Pw[gi * PADK + nt * 8 + 2 * ti] =
                make_float2(tf32r(sfr[nt][0]), tf32r(sfr[nt][1]));
            *(float2*)&Pw[(gi + 8) * PADK + nt * 8 + 2 * ti] =
                make_float2(tf32r(sfr[nt][2]), tf32r(sfr[nt][3]));
        }
        __syncwarp();

        // O += P @ V
        #pragma unroll
        for (int kc = 0; kc < 8; kc++) {
            const int kk = kc * 8 + ti;
            uint32_t af[4];
            af[0] = __float_as_uint(Pw[gi * PADK + kk]);
            af[1] = __float_as_uint(Pw[(gi + 8) * PADK + kk]);
            af[2] = __float_as_uint(Pw[gi * PADK + kk + 4]);
            af[3] = __float_as_uint(Pw[(gi + 8) * PADK + kk + 4]);
            #pragma unroll
            for (int nt = 0; nt < 8; nt++) {
                uint32_t bf[2];
                bf[0] = __float_as_uint(Vs[kk * PADV + nt * 8 + gi]);
                bf[1] = __float_as_uint(Vs[(kk + 4) * PADV + nt * 8 + gi]);
                mma_tf32(oacc[nt], af, bf);
            }
        }
        __syncwarp();   // Pw reads done before next iter overwrites
    }

    // Normalize + store to g_A[b][s][h*64+d]
    const int b = bh >> 4, h = bh & 15;
    const float inv0 = 1.0f / l0, inv1 = 1.0f / l1;
    const int r0 = q0 + w * 16 + gi, r1 = r0 + 8;
    float* base0 = g_A + ((size_t)(b * SEQ + r0)) * DMODEL + h * DHEAD;
    float* base1 = g_A + ((size_t)(b * SEQ + r1)) * DMODEL + h * DHEAD;
    #pragma unroll
    for (int nt = 0; nt < 8; nt++) {
        const int col = nt * 8 + 2 * ti;
        *(float2*)(base0 + col) = make_float2(oacc[nt][0] * inv0, oacc[nt][1] * inv0);
        *(float2*)(base1 + col) = make_float2(oacc[nt][2] * inv1, oacc[nt][3] * inv1);
    }
}

// ---------------------------------------------------------------------------

extern "C" void kernel_launch(void* const* d_in, const int* in_sizes, int n_in,
                              void* d_out, int out_size)
{
    const float* x  = (const float*)d_in[0];
    const float* Wq = (const float*)d_in[1];
    const float* Wk = (const float*)d_in[2];
    const float* Wv = (const float*)d_in[3];
    const float* Wo = (const float*)d_in[4];
    float* out = (float*)d_out;

    cudaFuncSetAttribute(gemm_tf32<0>, cudaFuncAttributeMaxDynamicSharedMemorySize, 65536);
    cudaFuncSetAttribute(gemm_tf32<1>, cudaFuncAttributeMaxDynamicSharedMemorySize, 65536);
    cudaFuncSetAttribute(flash_tc, cudaFuncAttributeMaxDynamicSharedMemorySize,
                         FLASH_SMEM_FLOATS * (int)sizeof(float));

    dim3 g1(DMODEL / 128, (BATCH * SEQ) / 128, 3);
    gemm_tf32<0><<<g1, 256, 65536>>>(x, Wq, Wk, Wv, nullptr);

    flash_tc<<<dim3(SEQ / FBQ, BATCH * NHEAD), 256,
               FLASH_SMEM_FLOATS * (int)sizeof(float)>>>();

    dim3 g2(DMODEL / 128, (BATCH * SEQ) / 128, 1);
    gemm_tf32<1><<<g2, 256, 65536>>>(x, Wo, nullptr, nullptr, out);
}

// round 11
// speedup vs baseline: 2.7506x; 1.1652x over previous
#include <cuda_runtime.h>
#include <stdint.h>
#include <math.h>

// Problem constants: B=4, S=2048, D=1024, H=16, dh=64
#define BATCH 4
#define SEQ   2048
#define DMODEL 1024
#define NHEAD 16
#define DHEAD 64

// Scratch (alloc-free rule: __device__ globals)
__device__ float g_Q[(size_t)BATCH * NHEAD * SEQ * DHEAD]; // [b][h][s][d] tf32
__device__ float g_K[(size_t)BATCH * NHEAD * SEQ * DHEAD]; // tf32
__device__ float g_V[(size_t)BATCH * NHEAD * SEQ * DHEAD]; // tf32
__device__ float g_A[(size_t)BATCH * SEQ * DMODEL];        // attn out, tf32
__device__ float g_Xr[(size_t)BATCH * SEQ * DMODEL];       // tf32-rounded x
__device__ float g_Wqr[(size_t)DMODEL * DMODEL];
__device__ float g_Wkr[(size_t)DMODEL * DMODEL];
__device__ float g_Wvr[(size_t)DMODEL * DMODEL];
__device__ float g_Wor[(size_t)DMODEL * DMODEL];

// ---------------------------------------------------------------------------
// Helpers
// ---------------------------------------------------------------------------
__device__ __forceinline__ void cp16(uint32_t dst, const void* src) {
    asm volatile("cp.async.cg.shared.global [%0], [%1], 16;" :: "r"(dst), "l"(src));
}

__device__ __forceinline__ float tf32r(float x) {
    uint32_t u;
    asm("cvt.rna.tf32.f32 %0, %1;" : "=r"(u) : "f"(x));
    return __uint_as_float(u);
}

__device__ __forceinline__ void mma_tf32(float c[4], const uint32_t a[4],
                                         const uint32_t b[2]) {
    asm volatile(
        "mma.sync.aligned.m16n8k8.row.col.f32.tf32.tf32.f32 "
        "{%0,%1,%2,%3}, {%4,%5,%6,%7}, {%8,%9}, {%0,%1,%2,%3};"
        : "+f"(c[0]), "+f"(c[1]), "+f"(c[2]), "+f"(c[3])
        : "r"(a[0]), "r"(a[1]), "r"(a[2]), "r"(a[3]), "r"(b[0]), "r"(b[1]));
}

// ---------------------------------------------------------------------------
// Pre-round pass: x and all 4 weights -> tf32(RNA) scratch (float4 vectorized)
// ---------------------------------------------------------------------------
#define XR_F4 ((size_t)BATCH * SEQ * DMODEL / 4)   // 2M float4
#define W_F4  ((size_t)DMODEL * DMODEL / 4)        // 256K float4
#define RP_TOTAL (XR_F4 + 4 * W_F4)                // 3M float4

__global__ __launch_bounds__(256) void round_pass(
    const float4* __restrict__ x,  const float4* __restrict__ wq,
    const float4* __restrict__ wk, const float4* __restrict__ wv,
    const float4* __restrict__ wo)
{
    size_t i = (size_t)blockIdx.x * blockDim.x + threadIdx.x;
    if (i >= RP_TOTAL) return;
    const float4* src; float4* dst; size_t j;
    if (i < XR_F4)                { src = x;  dst = (float4*)g_Xr;  j = i; }
    else {
        size_t k = i - XR_F4; int sel = (int)(k / W_F4); j = k % W_F4;
        src = (sel == 0) ? wq : (sel == 1) ? wk : (sel == 2) ? wv : wo;
        dst = (float4*)((sel == 0) ? g_Wqr : (sel == 1) ? g_Wkr
                       : (sel == 2) ? g_Wvr : g_Wor);
    }
    float4 v = src[j];
    dst[j] = make_float4(tf32r(v.x), tf32r(v.y), tf32r(v.z), tf32r(v.w));
}

// ---------------------------------------------------------------------------
// TF32 tensor-core GEMM (R9-proven addressing; inputs pre-rounded -> no CVT
// in the consume loop; swizzle slot hoisted per k8-step).
// C[m][n] = sum_k A[m][k] * W[n][k]. 128x128 tile, BK=32, 8 warps (2m x 4n).
// Smem elem (r,k) at float idx r*32 + ((k>>2)^(r&7))*4 + (k&3).
// MODE 0: z selects Q/K/V weights; epilogue fuses RoPE, stores tf32-rounded,
//         scatters to [b][h][s][dh]. MODE 1: plain row-major store to out.
// ---------------------------------------------------------------------------
template <int MODE>
__global__ __launch_bounds__(256) void gemm_tf32(float* __restrict__ Cout)
{
    extern __shared__ float gsm[];          // 64KB: A0, B0, A1, B1 (16KB each)
    const int z = (MODE == 0) ? blockIdx.z : 0;
    const float* Ain = (MODE == 0) ? g_Xr : g_A;
    const float* W = (MODE == 0) ? ((z == 0) ? g_Wqr : (z == 1) ? g_Wkr : g_Wvr)
                                 : g_Wor;
    float* Out = (MODE == 0) ? ((z == 0) ? g_Q : (z == 1) ? g_K : g_V) : Cout;

    const int m0 = blockIdx.y * 128, n0 = blockIdx.x * 128;
    const int t = threadIdx.x;
    const int lane = t & 31, wid = t >> 5;
    const int wm = wid >> 2, wn = wid & 3;
    const int gi = lane >> 2, ti = lane & 3;

    float* Ab[2] = {gsm, gsm + 8192};
    float* Bb[2] = {gsm + 4096, gsm + 12288};
    uint32_t sb;
    asm("{ .reg .u64 u; cvta.to.shared.u64 u, %1; cvt.u32.u64 %0, u; }"
        : "=r"(sb) : "l"(gsm));
    const uint32_t aoff0 = sb, aoff1 = sb + 8192 * 4;
    const uint32_t boff0 = sb + 4096 * 4, boff1 = sb + 12288 * 4;

    const int rr = t >> 3, cg = t & 7;
    const float* Ag = Ain + (size_t)(m0 + rr) * DMODEL + cg * 4;
    const float* Bg = W + (size_t)(n0 + rr) * DMODEL + cg * 4;
    const uint32_t dsw = (uint32_t)(rr * 32 + ((cg ^ (rr & 7)) << 2)) * 4;

    // Per-lane fragment row bases (float index). row&7 == gi for all rows.
    int aBase[4], bBase[4];
    #pragma unroll
    for (int mi = 0; mi < 4; mi++) aBase[mi] = (wm * 64 + mi * 16 + gi) * 32 + ti;
    #pragma unroll
    for (int ni = 0; ni < 4; ni++) bBase[ni] = (wn * 32 + ni * 8 + gi) * 32 + ti;

    float acc[4][4][4];
    #pragma unroll
    for (int mi = 0; mi < 4; mi++)
        #pragma unroll
        for (int ni = 0; ni < 4; ni++)
            #pragma unroll
            for (int c = 0; c < 4; c++) acc[mi][ni][c] = 0.0f;

    auto stage = [&](int buf, int kt) {
        const float* ag = Ag + kt * 32;
        const float* bg = Bg + kt * 32;
        uint32_t ad = (buf ? aoff1 : aoff0) + dsw;
        uint32_t bd = (buf ? boff1 : boff0) + dsw;
        #pragma unroll
        for (int i = 0; i < 4; i++) {
            cp16(ad + i * 4096, ag + (size_t)i * 32 * DMODEL);
            cp16(bd + i * 4096, bg + (size_t)i * 32 * DMODEL);
        }
        asm volatile("cp.async.commit_group;");
    };

    stage(0, 0);
    for (int kt = 0; kt < DMODEL / 32; kt++) {
        const int buf = kt & 1;
        asm volatile("cp.async.wait_group 0;");
        __syncthreads();
        if (kt < DMODEL / 32 - 1) stage(buf ^ 1, kt + 1);

        const float* Sa = Ab[buf];
        const float* Sb = Bb[buf];
        #pragma unroll
        for (int ks = 0; ks < 4; ks++) {
            const int s0 = ((2 * ks) ^ gi) << 2;        // k-group 2ks slot
            const int s1 = ((2 * ks + 1) ^ gi) << 2;    // k-group 2ks+1 slot
            uint32_t af[4][4];
            #pragma unroll
            for (int mi = 0; mi < 4; mi++) {
                af[mi][0] = __float_as_uint(Sa[aBase[mi] + s0]);
                af[mi][1] = __float_as_uint(Sa[aBase[mi] + 256 + s0]);
                af[mi][2] = __float_as_uint(Sa[aBase[mi] + s1]);
                af[mi][3] = __float_as_uint(Sa[aBase[mi] + 256 + s1]);
            }
            uint32_t bf[4][2];
            #pragma unroll
            for (int ni = 0; ni < 4; ni++) {
                bf[ni][0] = __float_as_uint(Sb[bBase[ni] + s0]);
                bf[ni][1] = __float_as_uint(Sb[bBase[ni] + s1]);
            }
            #pragma unroll
            for (int mi = 0; mi < 4; mi++)
                #pragma unroll
                for (int ni = 0; ni < 4; ni++)
                    mma_tf32(acc[mi][ni], af[mi], bf[ni]);
        }
    }

    // Epilogue. c0=(r,c), c1=(r,c+1), c2=(r+8,c), c3=(r+8,c+1); c even.
    #pragma unroll
    for (int mi = 0; mi < 4; mi++) {
        #pragma unroll
        for (int ni = 0; ni < 4; ni++) {
            const int row = m0 + wm * 64 + mi * 16 + gi;
            const int col = n0 + wn * 32 + ni * 8 + 2 * ti;
            const float c0 = acc[mi][ni][0], c1 = acc[mi][ni][1];
            const float c2 = acc[mi][ni][2], c3 = acc[mi][ni][3];
            if (MODE == 1) {
                *(float2*)(Out + (size_t)row * DMODEL + col) = make_float2(c0, c1);
                *(float2*)(Out + (size_t)(row + 8) * DMODEL + col) = make_float2(c2, c3);
            } else {
                const int h = col >> 6, dq = col & 63;
                const int s0 = row & (SEQ - 1), bb = row >> 11;
                float* d0 = Out + (((size_t)(bb * NHEAD + h) * SEQ + s0) * DHEAD + dq);
                float* d1 = d0 + 8 * DHEAD;
                if (z < 2) {
                    const int fi = dq >> 1;
                    const float inv = exp2f(-0.41524101186092356f * (float)fi);
                    float sn, cs;
                    sincosf((float)s0 * inv, &sn, &cs);
                    *(float2*)d0 = make_float2(tf32r(c0 * cs - c1 * sn),
                                               tf32r(c0 * sn + c1 * cs));
                    sincosf((float)(s0 + 8) * inv, &sn, &cs);
                    *(float2*)d1 = make_float2(tf32r(c2 * cs - c3 * sn),
                                               tf32r(c2 * sn + c3 * cs));
                } else {
                    *(float2*)d0 = make_float2(tf32r(c0), tf32r(c1));
                    *(float2*)d1 = make_float2(tf32r(c2), tf32r(c3));
                }
            }
        }
    }
}

// ---------------------------------------------------------------------------
// Tensor-core flash attention (tf32). Q/K/V arrive tf32-rounded -> no CVT in
// the staging loops (Q*0.125 is exact). O stored tf32-rounded for out GEMM.
// BQ=128 (8 warps x 16 q-rows), BK=64. Otherwise identical to passing R9.
// ---------------------------------------------------------------------------
#define FBQ 128
#define FBK 64
#define PADK 68
#define PADV 72
#define FLASH_SMEM_FLOATS (128*PADK + 64*PADK + 64*PADV + 8*16*PADK)

__global__ __launch_bounds__(256, 2) void flash_tc()
{
    extern __shared__ float sm[];
    float* Qs = sm;                          // [128][68]
    float* Ks = Qs + 128 * PADK;             // [64][68]
    float* Vs = Ks + 64 * PADK;              // [64][72]
    float* Ps = Vs + 64 * PADV;              // [8][16][68]

    const int qt = (int)gridDim.x - 1 - (int)blockIdx.x;   // heavy blocks first
    const int bh = blockIdx.y;
    const float* Qb = g_Q + (size_t)bh * SEQ * DHEAD;
    const float* Kb = g_K + (size_t)bh * SEQ * DHEAD;
    const float* Vb = g_V + (size_t)bh * SEQ * DHEAD;

    const int tid = threadIdx.x;
    const int lane = tid & 31, w = tid >> 5;
    const int gi = lane >> 2, ti = lane & 3;
    const int q0 = qt * FBQ;
    const int wq0 = q0 + w * 16;
    float* Pw = Ps + w * 16 * PADK;

    {
        const int r = tid >> 1;
        const int cb = (tid & 1) * 32;
        #pragma unroll
        for (int j = 0; j < 8; j++) {
            float4 v = *(const float4*)(Qb + (size_t)(q0 + r) * DHEAD + cb + j * 4);
            *(float4*)&Qs[r * PADK + cb + j * 4] =
                make_float4(v.x * 0.125f, v.y * 0.125f, v.z * 0.125f, v.w * 0.125f);
        }
    }

    float oacc[8][4];
    #pragma unroll
    for (int nt = 0; nt < 8; nt++)
        #pragma unroll
        for (int c = 0; c < 4; c++) oacc[nt][c] = 0.0f;
    float m0 = -1e30f, m1 = -1e30f, l0 = 0.0f, l1 = 0.0f;

    const int nkt = 2 * (qt + 1);
    for (int kt = 0; kt < nkt; kt++) {
        const int k0 = kt * FBK;
        __syncthreads();
        {
            const int r = tid >> 2;
            const int cb = (tid & 3) * 16;
            #pragma unroll
            for (int j = 0; j < 4; j++) {
                *(float4*)&Ks[r * PADK + cb + j * 4] =
                    *(const float4*)(Kb + (size_t)(k0 + r) * DHEAD + cb + j * 4);
                *(float4*)&Vs[r * PADV + cb + j * 4] =
                    *(const float4*)(Vb + (size_t)(k0 + r) * DHEAD + cb + j * 4);
            }
        }
        __syncthreads();

        float sfr[8][4];
        #pragma unroll
        for (int nt = 0; nt < 8; nt++)
            #pragma unroll
            for (int c = 0; c < 4; c++) sfr[nt][c] = 0.0f;

        #pragma unroll
        for (int kc = 0; kc < 8; kc++) {
            const int kk = kc * 8 + ti;
            uint32_t af[4];
            af[0] = __float_as_uint(Qs[(w * 16 + gi) * PADK + kk]);
            af[1] = __float_as_uint(Qs[(w * 16 + gi + 8) * PADK + kk]);
            af[2] = __float_as_uint(Qs[(w * 16 + gi) * PADK + kk + 4]);
            af[3] = __float_as_uint(Qs[(w * 16 + gi + 8) * PADK + kk + 4]);
            #pragma unroll
            for (int nt = 0; nt < 8; nt++) {
                uint32_t bf[2];
                bf[0] = __float_as_uint(Ks[(nt * 8 + gi) * PADK + kk]);
                bf[1] = __float_as_uint(Ks[(nt * 8 + gi) * PADK + kk + 4]);
                mma_tf32(sfr[nt], af, bf);
            }
        }

        if (k0 + FBK - 1 > wq0) {
            const int r0 = wq0 + gi, r1 = wq0 + gi + 8;
            #pragma unroll
            for (int nt = 0; nt < 8; nt++) {
                const int col = k0 + nt * 8 + 2 * ti;
                if (col > r0)     sfr[nt][0] = -1e30f;
                if (col + 1 > r0) sfr[nt][1] = -1e30f;
                if (col > r1)     sfr[nt][2] = -1e30f;
                if (col + 1 > r1) sfr[nt][3] = -1e30f;
            }
        }

        float mx0 = -1e30f, mx1 = -1e30f;
        #pragma unroll
        for (int nt = 0; nt < 8; nt++) {
            mx0 = fmaxf(mx0, fmaxf(sfr[nt][0], sfr[nt][1]));
            mx1 = fmaxf(mx1, fmaxf(sfr[nt][2], sfr[nt][3]));
        }
        #pragma unroll
        for (int off = 1; off < 4; off <<= 1) {
            mx0 = fmaxf(mx0, __shfl_xor_sync(0xffffffffu, mx0, off));
            mx1 = fmaxf(mx1, __shfl_xor_sync(0xffffffffu, mx1, off));
        }
        const float mn0 = fmaxf(m0, mx0), mn1 = fmaxf(m1, mx1);
        const float al0 = __expf(m0 - mn0), al1 = __expf(m1 - mn1);
        m0 = mn0; m1 = mn1;

        float s0 = 0.0f, s1 = 0.0f;
        #pragma unroll
        for (int nt = 0; nt < 8; nt++) {
            sfr[nt][0] = __expf(sfr[nt][0] - mn0);
            sfr[nt][1] = __expf(sfr[nt][1] - mn0);
            sfr[nt][2] = __expf(sfr[nt][2] - mn1);
            sfr[nt][3] = __expf(sfr[nt][3] - mn1);
            s0 += sfr[nt][0] + sfr[nt][1];
            s1 += sfr[nt][2] + sfr[nt][3];
        }
        #pragma unroll
        for (int off = 1; off < 4; off <<= 1) {
            s0 += __shfl_xor_sync(0xffffffffu, s0, off);
            s1 += __shfl_xor_sync(0xffffffffu, s1, off);
        }
        l0 = l0 * al0 + s0;
        l1 = l1 * al1 + s1;
        #pragma unroll
        for (int nt = 0; nt < 8; nt++) {
            oacc[nt][0] *= al0; oacc[nt][1] *= al0;
            oacc[nt][2] *= al1; oacc[nt][3] *= al1;
        }

        #pragma unroll
        for (int nt = 0; nt < 8; nt++) {
            *(float2*)&Pw[gi * PADK + nt * 8 + 2 * ti] =
                make_float2(tf32r(sfr[nt][0]), tf32r(sfr[nt][1]));
            *(float2*)&Pw[(gi + 8) * PADK + nt * 8 + 2 * ti] =
                make_float2(tf32r(sfr[nt][2]), tf32r(sfr[nt][3]));
        }
        __syncwarp();

        #pragma unroll
        for (int kc = 0; kc < 8; kc++) {
            const int kk = kc * 8 + ti;
            uint32_t af[4];
            af[0] = __float_as_uint(Pw[gi * PADK + kk]);
            af[1] = __float_as_uint(Pw[(gi + 8) * PADK + kk]);
            af[2] = __float_as_uint(Pw[gi * PADK + kk + 4]);
            af[3] = __float_as_uint(Pw[(gi + 8) * PADK + kk + 4]);
            #pragma unroll
            for (int nt = 0; nt < 8; nt++) {
                uint32_t bf[2];
                bf[0] = __float_as_uint(Vs[kk * PADV + nt * 8 + gi]);
                bf[1] = __float_as_uint(Vs[(kk + 4) * PADV + nt * 8 + gi]);
                mma_tf32(oacc[nt], af, bf);
            }
        }
        __syncwarp();
    }

    // Normalize + store (tf32-rounded: feeds out GEMM with no in-loop cvt)
    const int b = bh >> 4, h = bh & 15;
    const float inv0 = 1.0f / l0, inv1 = 1.0f / l1;
    const int r0 = q0 + w * 16 + gi, r1 = r0 + 8;
    float* base0 = g_A + ((size_t)(b * SEQ + r0)) * DMODEL + h * DHEAD;
    float* base1 = g_A + ((size_t)(b * SEQ + r1)) * DMODEL + h * DHEAD;
    #pragma unroll
    for (int nt = 0; nt < 8; nt++) {
        const int col = nt * 8 + 2 * ti;
        *(float2*)(base0 + col) =
            make_float2(tf32r(oacc[nt][0] * inv0), tf32r(oacc[nt][1] * inv0));
        *(float2*)(base1 + col) =
            make_float2(tf32r(oacc[nt][2] * inv1), tf32r(oacc[nt][3] * inv1));
    }
}

// ---------------------------------------------------------------------------

extern "C" void kernel_launch(void* const* d_in, const int* in_sizes, int n_in,
                              void* d_out, int out_size)
{
    const float* x  = (const float*)d_in[0];
    const float* Wq = (const float*)d_in[1];
    const float* Wk = (const float*)d_in[2];
    const float* Wv = (const float*)d_in[3];
    const float* Wo = (const float*)d_in[4];
    float* out = (float*)d_out;

    cudaFuncSetAttribute(gemm_tf32<0>, cudaFuncAttributeMaxDynamicSharedMemorySize, 65536);
    cudaFuncSetAttribute(gemm_tf32<1>, cudaFuncAttributeMaxDynamicSharedMemorySize, 65536);
    cudaFuncSetAttribute(flash_tc, cudaFuncAttributeMaxDynamicSharedMemorySize,
                         FLASH_SMEM_FLOATS * (int)sizeof(float));

    round_pass<<<(unsigned)((RP_TOTAL + 255) / 256), 256>>>(
        (const float4*)x, (const float4*)Wq, (const float4*)Wk,
        (const float4*)Wv, (const float4*)Wo);

    dim3 g1(DMODEL / 128, (BATCH * SEQ) / 128, 3);
    gemm_tf32<0><<<g1, 256, 65536>>>(nullptr);

    flash_tc<<<dim3(SEQ / FBQ, BATCH * NHEAD), 256,
               FLASH_SMEM_FLOATS * (int)sizeof(float)>>>();

    dim3 g2(DMODEL / 128, (BATCH * SEQ) / 128, 1);
    gemm_tf32<1><<<g2, 256, 65536>>>(out);
}